// round 1
// baseline (speedup 1.0000x reference)
#include <cuda_runtime.h>
#include <math.h>

// Problem constants
#define BB  8
#define SS  1024
#define EE  512
#define HH  8
#define DD  64
#define BHn (BB*HH)          // 64
#define QT  32               // q rows per attention block

// ---------------------------------------------------------------------------
// Scratch (static __device__ arrays: allocation-free per harness rules)
// ---------------------------------------------------------------------------
__device__ float g_q[(size_t)BHn*SS*DD];     // [BH, S, D]
__device__ float g_k[(size_t)BHn*SS*DD];
__device__ float g_v[(size_t)BHn*SS*DD];
__device__ float g_kn[BHn*SS];               // k row norms
__device__ float g_vals[(size_t)BB*SS*EE];   // attn @ V, [B,S,E]

// ---------------------------------------------------------------------------
// QKV projection: C[8192,512] = x @ W + b, scattered to [BH,S,D]
// 64x64 block tile, BK=16, 256 threads, 4x4 per-thread microtile.
// blockIdx.z selects q/k/v.
// ---------------------------------------------------------------------------
__global__ void __launch_bounds__(256) proj_kernel(
    const float* __restrict__ x,
    const float* __restrict__ Wq, const float* __restrict__ bq,
    const float* __restrict__ Wk, const float* __restrict__ bk,
    const float* __restrict__ Wv, const float* __restrict__ bv)
{
    const float* W; const float* bias; float* outp;
    if (blockIdx.z == 0)      { W = Wq; bias = bq; outp = g_q; }
    else if (blockIdx.z == 1) { W = Wk; bias = bk; outp = g_k; }
    else                      { W = Wv; bias = bv; outp = g_v; }

    __shared__ float As[64][17];   // [m][k], pad to 17 to kill STS conflicts
    __shared__ float Bs[16][64];   // [k][n]

    const int tid  = threadIdx.x;
    const int tx   = tid & 15, ty = tid >> 4;       // 16x16 thread grid
    const int row0 = blockIdx.y * 64;
    const int col0 = blockIdx.x * 64;
    const int Arow = tid >> 2, Ac = (tid & 3) * 4;  // A loader mapping

    float acc[4][4] = {};

    for (int k0 = 0; k0 < EE; k0 += 16) {
        float4 a4 = *(const float4*)&x[(size_t)(row0 + Arow) * EE + k0 + Ac];
        float4 b4 = *(const float4*)&W[(size_t)(k0 + ty) * EE + col0 + tx*4];
        __syncthreads();
        As[Arow][Ac+0] = a4.x; As[Arow][Ac+1] = a4.y;
        As[Arow][Ac+2] = a4.z; As[Arow][Ac+3] = a4.w;
        *(float4*)&Bs[ty][tx*4] = b4;
        __syncthreads();
        #pragma unroll
        for (int kk = 0; kk < 16; kk++) {
            float4 bf = *(const float4*)&Bs[kk][tx*4];
            float a0 = As[ty*4+0][kk];
            float a1 = As[ty*4+1][kk];
            float a2 = As[ty*4+2][kk];
            float a3 = As[ty*4+3][kk];
            acc[0][0]+=a0*bf.x; acc[0][1]+=a0*bf.y; acc[0][2]+=a0*bf.z; acc[0][3]+=a0*bf.w;
            acc[1][0]+=a1*bf.x; acc[1][1]+=a1*bf.y; acc[1][2]+=a1*bf.z; acc[1][3]+=a1*bf.w;
            acc[2][0]+=a2*bf.x; acc[2][1]+=a2*bf.y; acc[2][2]+=a2*bf.z; acc[2][3]+=a2*bf.w;
            acc[3][0]+=a3*bf.x; acc[3][1]+=a3*bf.y; acc[3][2]+=a3*bf.z; acc[3][3]+=a3*bf.w;
        }
    }

    // Epilogue: bias + scatter to [BH,S,D]. Block's 64 cols == one head (D=64).
    float4 bv4 = *(const float4*)&bias[col0 + tx*4];
    const int h = blockIdx.x;  // col0 / 64
    #pragma unroll
    for (int i = 0; i < 4; i++) {
        int r  = row0 + ty*4 + i;
        int bb = r >> 10, ss = r & 1023;  // r / S, r % S  (S=1024)
        float4 o;
        o.x = acc[i][0] + bv4.x; o.y = acc[i][1] + bv4.y;
        o.z = acc[i][2] + bv4.z; o.w = acc[i][3] + bv4.w;
        *(float4*)&outp[((size_t)(bb*HH + h)*SS + ss)*DD + tx*4] = o;
    }
}

// ---------------------------------------------------------------------------
// k row norms: g_kn[r] = sum_d g_k[r][d]^2
// ---------------------------------------------------------------------------
__global__ void __launch_bounds__(256) knorm_kernel()
{
    int r = blockIdx.x * blockDim.x + threadIdx.x;
    if (r >= BHn*SS) return;
    const float* kp = g_k + (size_t)r * DD;
    float s = 0.f;
    #pragma unroll
    for (int i = 0; i < 16; i++) {
        float4 v = *(const float4*)&kp[i*4];
        s += v.x*v.x + v.y*v.y + v.z*v.z + v.w*v.w;
    }
    g_kn[r] = s;
}

// ---------------------------------------------------------------------------
// Fused attention: per (bh, 32-row q tile)
//   scores -> softmax + RBF + combine -> store attn -> attn @ V
// Score tile [32][1024] lives entirely in SMEM; attn is written once to gmem
// and never re-read (attn@V consumes the SMEM copy).
// ---------------------------------------------------------------------------
#define SMEM_FLOATS (QT*SS + QT*65 + 64*65 + SS)  // 40032 floats = 160128 B

__global__ void __launch_bounds__(512) attn_kernel(
    const float* __restrict__ pond, float* __restrict__ attn_out)
{
    extern __shared__ float sm[];
    float* sc = sm;                  // [32][1024] score/attn tile
    float* qs = sc + QT*SS;          // [32][65]   q tile (stride 65)
    float* ks = qs + QT*65;          // [64][65]   k/v tile (stride 65)
    float* kn = ks + 64*65;          // [1024]     k norms

    const int tid = threadIdx.x;
    const int tx  = tid & 15;        // col group: cols tx, tx+16, tx+32, tx+48
    const int ty  = tid >> 4;        // 0..31: one q row per thread
    const int bh  = blockIdx.x;
    const int q0  = blockIdx.y * QT;

    const float p      = pond[0];
    const float sv     = 1.f / (1.f + __expf(-p));
    const float p0     = 1.f - sv, p1 = sv;
    const float invden = 1.f / (p0 + p1 + 1e-7f);

    // load q tile (32x64 floats, one float4 per thread)
    {
        int r = tid >> 4, c = (tid & 15) * 4;
        float4 v = *(const float4*)&g_q[((size_t)bh*SS + q0 + r)*DD + c];
        float* d = qs + r*65 + c;
        d[0]=v.x; d[1]=v.y; d[2]=v.z; d[3]=v.w;
    }
    // load k norms for this bh
    for (int i = tid; i < SS; i += 512) kn[i] = g_kn[bh*SS + i];

    // ---- scores: sc[q][k] = q . k ----
    const float* kbase = g_k + (size_t)bh*SS*DD;
    for (int kt = 0; kt < 16; kt++) {
        __syncthreads();
        #pragma unroll
        for (int it = 0; it < 2; it++) {
            int f = tid + it*512;
            int r = f >> 4, c = (f & 15) * 4;
            float4 v = *(const float4*)&kbase[(size_t)(kt*64 + r)*DD + c];
            float* d = ks + r*65 + c;
            d[0]=v.x; d[1]=v.y; d[2]=v.z; d[3]=v.w;
        }
        __syncthreads();
        const float* qrow = qs + ty*65;
        const float* k0p  = ks + (tx     )*65;
        const float* k1p  = ks + (tx + 16)*65;
        const float* k2p  = ks + (tx + 32)*65;
        const float* k3p  = ks + (tx + 48)*65;
        float a0=0.f, a1=0.f, a2=0.f, a3=0.f;
        #pragma unroll
        for (int d = 0; d < 64; d++) {
            float q = qrow[d];
            a0 += q*k0p[d]; a1 += q*k1p[d]; a2 += q*k2p[d]; a3 += q*k3p[d];
        }
        float* srow = sc + ty*SS + kt*64;
        srow[tx] = a0; srow[tx+16] = a1; srow[tx+32] = a2; srow[tx+48] = a3;
    }
    __syncthreads();

    // ---- per-row softmax + RBF + combine; write attn ----
    const int warp = tid >> 5, lane = tid & 31;
    for (int rr = warp; rr < QT; rr += 16) {
        const float* qrow = qs + rr*65;
        float qv  = qrow[lane], qv2 = qrow[lane+32];
        float qn  = qv*qv + qv2*qv2;
        #pragma unroll
        for (int o = 16; o; o >>= 1) qn += __shfl_xor_sync(~0u, qn, o);

        float* srow = sc + rr*SS;
        float m = -1e30f;
        for (int c = lane; c < SS; c += 32) m = fmaxf(m, srow[c]);
        #pragma unroll
        for (int o = 16; o; o >>= 1) m = fmaxf(m, __shfl_xor_sync(~0u, m, o));

        const float sigma  = fminf(fmaxf(qn, 1e-8f), 1e4f);
        const float invsig = 1.f / sigma;
        float ssum = 0.f, rsum = 0.f;
        for (int c = lane; c < SS; c += 32) {
            float s = srow[c];
            ssum += __expf((s - m) * 0.125f);                 // 1/sqrt(D)=0.125
            float dist = fmaxf(qn + kn[c] - 2.f*s, 0.f);
            rsum += __expf(-dist * invsig);
        }
        #pragma unroll
        for (int o = 16; o; o >>= 1) {
            ssum += __shfl_xor_sync(~0u, ssum, o);
            rsum += __shfl_xor_sync(~0u, rsum, o);
        }
        const float cs = p0 * invden / ssum;
        const float cr = p1 * invden / fmaxf(rsum, 1e-8f);

        float* arow = attn_out + ((size_t)bh*SS + q0 + rr)*SS;
        for (int c = lane; c < SS; c += 32) {
            float s    = srow[c];
            float e    = __expf((s - m) * 0.125f);
            float dist = fmaxf(qn + kn[c] - 2.f*s, 0.f);
            float rb   = __expf(-dist * invsig);
            float a    = cs*e + cr*rb;
            srow[c] = a;
            arow[c] = a;
        }
    }
    __syncthreads();

    // ---- attn @ V ----
    float v0=0.f, v1=0.f, v2=0.f, v3=0.f;
    const float* vbase = g_v + (size_t)bh*SS*DD;
    for (int vt = 0; vt < 16; vt++) {
        __syncthreads();
        #pragma unroll
        for (int it = 0; it < 2; it++) {
            int f = tid + it*512;
            int r = f >> 4, c = (f & 15) * 4;
            float4 v = *(const float4*)&vbase[(size_t)(vt*64 + r)*DD + c];
            float* d = ks + r*65 + c;
            d[0]=v.x; d[1]=v.y; d[2]=v.z; d[3]=v.w;
        }
        __syncthreads();
        const float* srow = sc + ty*SS + vt*64;
        #pragma unroll
        for (int kk = 0; kk < 64; kk++) {
            float a = srow[kk];
            const float* vr = ks + kk*65;
            v0 += a*vr[tx]; v1 += a*vr[tx+16]; v2 += a*vr[tx+32]; v3 += a*vr[tx+48];
        }
    }
    const int bb = bh >> 3, hh = bh & 7;   // bh / H, bh % H
    float* vout = g_vals + ((size_t)(bb*SS + q0 + ty))*EE + hh*DD;
    vout[tx] = v0; vout[tx+16] = v1; vout[tx+32] = v2; vout[tx+48] = v3;
}

// ---------------------------------------------------------------------------
// Output projection: out[8192,512] = g_vals @ Wo + bo
// ---------------------------------------------------------------------------
__global__ void __launch_bounds__(256) out_kernel(
    const float* __restrict__ Wo, const float* __restrict__ bo,
    float* __restrict__ outp)
{
    __shared__ float As[64][17];
    __shared__ float Bs[16][64];

    const int tid  = threadIdx.x;
    const int tx   = tid & 15, ty = tid >> 4;
    const int row0 = blockIdx.y * 64;
    const int col0 = blockIdx.x * 64;
    const int Arow = tid >> 2, Ac = (tid & 3) * 4;

    float acc[4][4] = {};

    for (int k0 = 0; k0 < EE; k0 += 16) {
        float4 a4 = *(const float4*)&g_vals[(size_t)(row0 + Arow) * EE + k0 + Ac];
        float4 b4 = *(const float4*)&Wo[(size_t)(k0 + ty) * EE + col0 + tx*4];
        __syncthreads();
        As[Arow][Ac+0] = a4.x; As[Arow][Ac+1] = a4.y;
        As[Arow][Ac+2] = a4.z; As[Arow][Ac+3] = a4.w;
        *(float4*)&Bs[ty][tx*4] = b4;
        __syncthreads();
        #pragma unroll
        for (int kk = 0; kk < 16; kk++) {
            float4 bf = *(const float4*)&Bs[kk][tx*4];
            float a0 = As[ty*4+0][kk];
            float a1 = As[ty*4+1][kk];
            float a2 = As[ty*4+2][kk];
            float a3 = As[ty*4+3][kk];
            acc[0][0]+=a0*bf.x; acc[0][1]+=a0*bf.y; acc[0][2]+=a0*bf.z; acc[0][3]+=a0*bf.w;
            acc[1][0]+=a1*bf.x; acc[1][1]+=a1*bf.y; acc[1][2]+=a1*bf.z; acc[1][3]+=a1*bf.w;
            acc[2][0]+=a2*bf.x; acc[2][1]+=a2*bf.y; acc[2][2]+=a2*bf.z; acc[2][3]+=a2*bf.w;
            acc[3][0]+=a3*bf.x; acc[3][1]+=a3*bf.y; acc[3][2]+=a3*bf.z; acc[3][3]+=a3*bf.w;
        }
    }

    float4 bv4 = *(const float4*)&bo[col0 + tx*4];
    #pragma unroll
    for (int i = 0; i < 4; i++) {
        int r = row0 + ty*4 + i;
        float4 o;
        o.x = acc[i][0] + bv4.x; o.y = acc[i][1] + bv4.y;
        o.z = acc[i][2] + bv4.z; o.w = acc[i][3] + bv4.w;
        *(float4*)&outp[(size_t)r*EE + col0 + tx*4] = o;
    }
}

// ---------------------------------------------------------------------------
// d_out layout (reference returns (out, attn)):
//   [0, B*S*E)                     : out   fp32
//   [B*S*E, B*S*E + B*H*S*S)       : attn  fp32
// ---------------------------------------------------------------------------
extern "C" void kernel_launch(void* const* d_in, const int* in_sizes, int n_in,
                              void* d_out, int out_size)
{
    const float* x  = (const float*)d_in[0];
    const float* Wq = (const float*)d_in[1];
    const float* bq = (const float*)d_in[2];
    const float* Wk = (const float*)d_in[3];
    const float* bk = (const float*)d_in[4];
    const float* Wv = (const float*)d_in[5];
    const float* bv = (const float*)d_in[6];
    const float* Wo = (const float*)d_in[7];
    const float* bo = (const float*)d_in[8];
    const float* pp = (const float*)d_in[9];
    float* out = (float*)d_out;

    proj_kernel<<<dim3(EE/64, (BB*SS)/64, 3), 256>>>(x, Wq, bq, Wk, bk, Wv, bv);
    knorm_kernel<<<(BHn*SS)/256, 256>>>();

    cudaFuncSetAttribute(attn_kernel,
                         cudaFuncAttributeMaxDynamicSharedMemorySize,
                         SMEM_FLOATS * (int)sizeof(float));
    attn_kernel<<<dim3(BHn, SS/QT), 512, SMEM_FLOATS * sizeof(float)>>>(
        pp, out + (size_t)BB*SS*EE);

    out_kernel<<<dim3(EE/64, (BB*SS)/64), 256>>>(Wo, bo, out);
}

// round 2
// speedup vs baseline: 1.5024x; 1.5024x over previous
#include <cuda_runtime.h>
#include <math.h>

// Problem constants
#define BB  8
#define SS  1024
#define EE  512
#define HH  8
#define DD  64
#define BHn (BB*HH)          // 64
#define QT  32               // q rows per attention block
#define KT2 256              // k tile cols per iteration

typedef unsigned long long ull;

__device__ __forceinline__ ull pk2(float a, float b) {
    ull r; asm("mov.b64 %0,{%1,%2};" : "=l"(r) : "f"(a), "f"(b)); return r;
}
__device__ __forceinline__ void upk2(ull v, float& a, float& b) {
    asm("mov.b64 {%0,%1},%2;" : "=f"(a), "=f"(b) : "l"(v));
}
__device__ __forceinline__ ull fma2(ull a, ull b, ull c) {
    ull d; asm("fma.rn.f32x2 %0,%1,%2,%3;" : "=l"(d) : "l"(a), "l"(b), "l"(c)); return d;
}

// ---------------------------------------------------------------------------
// Scratch
// ---------------------------------------------------------------------------
__device__ float g_q[(size_t)BHn*SS*DD];     // [BH, S, D]
__device__ float g_k[(size_t)BHn*SS*DD];
__device__ float g_v[(size_t)BHn*SS*DD];
__device__ float g_kn[BHn*SS];
__device__ float g_vals[(size_t)BB*SS*EE];   // [B,S,E]

// ---------------------------------------------------------------------------
// QKV projection: 64x128 block tile, BK=16, 256 threads, 4x8 microtile (f32x2)
// ---------------------------------------------------------------------------
__global__ void __launch_bounds__(256) proj_kernel(
    const float* __restrict__ x,
    const float* __restrict__ Wq, const float* __restrict__ bq,
    const float* __restrict__ Wk, const float* __restrict__ bk,
    const float* __restrict__ Wv, const float* __restrict__ bv)
{
    const float* W; const float* bias; float* outp;
    if (blockIdx.z == 0)      { W = Wq; bias = bq; outp = g_q; }
    else if (blockIdx.z == 1) { W = Wk; bias = bk; outp = g_k; }
    else                      { W = Wv; bias = bv; outp = g_v; }

    __shared__ float As[64*17];     // [m][k] stride 17
    __shared__ float Bs[16*132];    // [k][n] stride 132 (float4-aligned, conflict-free pairs)

    const int tid  = threadIdx.x;
    const int tx   = tid & 15, ty = tid >> 4;
    const int row0 = blockIdx.y * 64;
    const int col0 = blockIdx.x * 128;
    const int Arow = tid >> 2, Ac = (tid & 3) * 4;
    const int Br   = tid >> 5, Bc = (tid & 31) * 4;

    ull acc[4][4];
    #pragma unroll
    for (int j = 0; j < 4; j++)
        #pragma unroll
        for (int i = 0; i < 4; i++) acc[j][i] = 0ull;

    for (int k0 = 0; k0 < EE; k0 += 16) {
        float4 a4 = *(const float4*)&x[(size_t)(row0 + Arow)*EE + k0 + Ac];
        float4 b0 = *(const float4*)&W[(size_t)(k0 + Br    )*EE + col0 + Bc];
        float4 b1 = *(const float4*)&W[(size_t)(k0 + Br + 8)*EE + col0 + Bc];
        __syncthreads();
        As[Arow*17 + Ac+0] = a4.x; As[Arow*17 + Ac+1] = a4.y;
        As[Arow*17 + Ac+2] = a4.z; As[Arow*17 + Ac+3] = a4.w;
        *(float4*)&Bs[(Br    )*132 + Bc] = b0;
        *(float4*)&Bs[(Br + 8)*132 + Bc] = b1;
        __syncthreads();
        #pragma unroll
        for (int kk = 0; kk < 16; kk++) {
            ull bp[4];
            #pragma unroll
            for (int i = 0; i < 4; i++)
                bp[i] = *(const ull*)&Bs[kk*132 + 2*tx + 32*i];
            #pragma unroll
            for (int j = 0; j < 4; j++) {
                float a = As[(ty*4+j)*17 + kk];
                ull aa = pk2(a, a);
                #pragma unroll
                for (int i = 0; i < 4; i++)
                    acc[j][i] = fma2(aa, bp[i], acc[j][i]);
            }
        }
    }

    // Epilogue: bias + scatter to [BH,S,D]
    #pragma unroll
    for (int i = 0; i < 4; i++) {
        int c    = col0 + 2*tx + 32*i;       // even; pair (c, c+1) same head
        int head = c >> 6, dd = c & 63;
        float blo = bias[c], bhi = bias[c+1];
        #pragma unroll
        for (int j = 0; j < 4; j++) {
            int r  = row0 + ty*4 + j;
            int bb = r >> 10, ss = r & 1023;
            float lo, hi; upk2(acc[j][i], lo, hi);
            float2 o; o.x = lo + blo; o.y = hi + bhi;
            *(float2*)&outp[((size_t)(bb*HH + head)*SS + ss)*DD + dd] = o;
        }
    }
}

// ---------------------------------------------------------------------------
// k row norms
// ---------------------------------------------------------------------------
__global__ void __launch_bounds__(256) knorm_kernel()
{
    int r = blockIdx.x * blockDim.x + threadIdx.x;
    if (r >= BHn*SS) return;
    const float* kp = g_k + (size_t)r * DD;
    float s = 0.f;
    #pragma unroll
    for (int i = 0; i < 16; i++) {
        float4 v = *(const float4*)&kp[i*4];
        s += v.x*v.x + v.y*v.y + v.z*v.z + v.w*v.w;
    }
    g_kn[r] = s;
}

// ---------------------------------------------------------------------------
// Fused attention per (bh, 32-row q tile):
//   scores (4q x 8k microtile, f32x2) -> softmax+RBF (no max pass)
//   -> attn write -> attn @ V (4-way k-split, f32x2) -> reduce
// ---------------------------------------------------------------------------
#define SC_F   (QT*SS)          // 32768
#define KV_F   (KT2*66)         // 16896
#define QS_F   (QT*65)          // 2080
#define SMF    (SC_F + KV_F + QS_F + SS)   // 52768 floats = 211072 B

__global__ void __launch_bounds__(256) attn_kernel(
    const float* __restrict__ pond, float* __restrict__ attn_out)
{
    extern __shared__ float sm[];
    float* sc = sm;                 // [32][1024] scores / attn / AV-partials
    float* kv = sc + SC_F;          // k tile [256][65] (score) / v tile [256][66] (AV)
    float* qs = kv + KV_F;          // [32][65]
    float* kn = qs + QS_F;          // [1024]

    const int tid = threadIdx.x;
    const int bh  = blockIdx.x;
    const int q0  = blockIdx.y * QT;

    const float p      = pond[0];
    const float sv     = 1.f / (1.f + __expf(-p));
    const float p0     = 1.f - sv, p1 = sv;
    const float invden = 1.f / (p0 + p1 + 1e-7f);

    // load q tile (32x64) and k norms
    #pragma unroll
    for (int it = 0; it < 2; it++) {
        int f = tid + it*256;
        int r = f >> 4, c = (f & 15) * 4;
        float4 v = *(const float4*)&g_q[((size_t)bh*SS + q0 + r)*DD + c];
        float* d = qs + r*65 + c;
        d[0]=v.x; d[1]=v.y; d[2]=v.z; d[3]=v.w;
    }
    for (int i = tid; i < SS; i += 256) kn[i] = g_kn[bh*SS + i];

    const int tx = tid & 31;        // k col: tx + 32*i, i=0..7
    const int ty = tid >> 5;        // q rows ty*4 .. ty*4+3

    // ---- scores ----
    const float* kbase = g_k + (size_t)bh*SS*DD;
    for (int kt = 0; kt < 4; kt++) {
        __syncthreads();
        #pragma unroll
        for (int it = 0; it < 16; it++) {
            int f = tid + it*256;
            int r = f >> 4, c = (f & 15) * 4;
            float4 v = *(const float4*)&kbase[(size_t)(kt*KT2 + r)*DD + c];
            float* d = kv + r*65 + c;
            d[0]=v.x; d[1]=v.y; d[2]=v.z; d[3]=v.w;
        }
        __syncthreads();

        ull acc[4][4];
        #pragma unroll
        for (int j = 0; j < 4; j++)
            #pragma unroll
            for (int pp = 0; pp < 4; pp++) acc[j][pp] = 0ull;

        const float* qb = qs + ty*4*65;
        const float* kb = kv + tx*65;
        #pragma unroll 4
        for (int d = 0; d < 64; d++) {
            // pair pp combines cols (tx+64pp, tx+64pp+32)
            ull kp0 = pk2(kb[d + 0*65],   kb[d + 32*65]);
            ull kp1 = pk2(kb[d + 64*65],  kb[d + 96*65]);
            ull kp2 = pk2(kb[d + 128*65], kb[d + 160*65]);
            ull kp3 = pk2(kb[d + 192*65], kb[d + 224*65]);
            #pragma unroll
            for (int j = 0; j < 4; j++) {
                float q = qb[j*65 + d];
                ull qq = pk2(q, q);
                acc[j][0] = fma2(qq, kp0, acc[j][0]);
                acc[j][1] = fma2(qq, kp1, acc[j][1]);
                acc[j][2] = fma2(qq, kp2, acc[j][2]);
                acc[j][3] = fma2(qq, kp3, acc[j][3]);
            }
        }
        #pragma unroll
        for (int j = 0; j < 4; j++) {
            float* srow = sc + (ty*4+j)*SS + kt*KT2;
            #pragma unroll
            for (int pp = 0; pp < 4; pp++) {
                float lo, hi; upk2(acc[j][pp], lo, hi);
                srow[tx + 64*pp]      = lo;
                srow[tx + 64*pp + 32] = hi;
            }
        }
    }
    __syncthreads();

    // ---- softmax + RBF + combine (no max pass: |s|*0.125 << 80, exp safe) ----
    {
        const int warp = tid >> 5, lane = tid & 31;
        for (int rr = warp; rr < QT; rr += 8) {
            const float* qrow = qs + rr*65;
            float qv = qrow[lane], qv2 = qrow[lane+32];
            float qn = qv*qv + qv2*qv2;
            #pragma unroll
            for (int o = 16; o; o >>= 1) qn += __shfl_xor_sync(~0u, qn, o);

            const float sigma  = fminf(fmaxf(qn, 1e-8f), 1e4f);
            const float invsig = 1.f / sigma;
            float* srow = sc + rr*SS;
            float ssum = 0.f, rsum = 0.f;
            for (int c = lane; c < SS; c += 32) {
                float s = srow[c];
                ssum += __expf(s * 0.125f);
                float dist = fmaxf(qn + kn[c] - 2.f*s, 0.f);
                rsum += __expf(-dist * invsig);
            }
            #pragma unroll
            for (int o = 16; o; o >>= 1) {
                ssum += __shfl_xor_sync(~0u, ssum, o);
                rsum += __shfl_xor_sync(~0u, rsum, o);
            }
            const float cs = p0 * invden / ssum;
            const float cr = p1 * invden / fmaxf(rsum, 1e-8f);

            float* arow = attn_out + ((size_t)bh*SS + q0 + rr)*SS;
            for (int c = lane; c < SS; c += 32) {
                float s    = srow[c];
                float e    = __expf(s * 0.125f);
                float dist = fmaxf(qn + kn[c] - 2.f*s, 0.f);
                float a    = cs*e + cr*__expf(-dist * invsig);
                srow[c] = a;
                arow[c] = a;
            }
        }
    }
    __syncthreads();

    // ---- attn @ V : 4-way k-split across lane groups ----
    // lane = kg*8 + dg ; thread owns d = 2*dg + 16*pp (+1), q rows w*4+j
    const int lane = tid & 31, w = tid >> 5;
    const int dg = lane & 7, kg = lane >> 3;

    ull vacc[4][4];
    #pragma unroll
    for (int j = 0; j < 4; j++)
        #pragma unroll
        for (int pp = 0; pp < 4; pp++) vacc[j][pp] = 0ull;

    const float* vbase = g_v + (size_t)bh*SS*DD;
    for (int vt = 0; vt < 4; vt++) {
        __syncthreads();
        #pragma unroll
        for (int it = 0; it < 16; it++) {
            int f = tid + it*256;
            int r = f >> 4, c = (f & 15) * 4;
            float4 v = *(const float4*)&vbase[(size_t)(vt*KT2 + r)*DD + c];
            float* d = kv + r*66 + c;
            d[0]=v.x; d[1]=v.y; d[2]=v.z; d[3]=v.w;
        }
        __syncthreads();

        #pragma unroll 2
        for (int kk = 0; kk < 64; kk++) {
            int kl = kg*64 + ((kk + kg*8) & 63);   // bank-staggered per group
            const float* vr = kv + kl*66 + 2*dg;
            ull v0 = *(const ull*)(vr +  0);
            ull v1 = *(const ull*)(vr + 16);
            ull v2 = *(const ull*)(vr + 32);
            ull v3 = *(const ull*)(vr + 48);
            const float* acol = sc + vt*KT2 + kl;
            #pragma unroll
            for (int j = 0; j < 4; j++) {
                float a = acol[(w*4+j)*SS];
                ull aa = pk2(a, a);
                vacc[j][0] = fma2(aa, v0, vacc[j][0]);
                vacc[j][1] = fma2(aa, v1, vacc[j][1]);
                vacc[j][2] = fma2(aa, v2, vacc[j][2]);
                vacc[j][3] = fma2(aa, v3, vacc[j][3]);
            }
        }
    }
    __syncthreads();

    // partials -> sc[kg*2048 + row*64 + d]
    #pragma unroll
    for (int j = 0; j < 4; j++)
        #pragma unroll
        for (int pp = 0; pp < 4; pp++) {
            float lo, hi; upk2(vacc[j][pp], lo, hi);
            float* dst = sc + kg*2048 + (w*4+j)*64 + 2*dg + 16*pp;
            dst[0] = lo; dst[1] = hi;
        }
    __syncthreads();

    // reduce 4 partials, write to g_vals
    const int bb = bh >> 3, hh = bh & 7;
    for (int idx = tid; idx < 2048; idx += 256) {
        float vsum = sc[idx] + sc[2048+idx] + sc[4096+idx] + sc[6144+idx];
        int row = idx >> 6, d = idx & 63;
        g_vals[((size_t)(bb*SS + q0 + row))*EE + hh*DD + d] = vsum;
    }
}

// ---------------------------------------------------------------------------
// Output projection: out = g_vals @ Wo + bo  (same 4x8 f32x2 scheme)
// ---------------------------------------------------------------------------
__global__ void __launch_bounds__(256) out_kernel(
    const float* __restrict__ Wo, const float* __restrict__ bo,
    float* __restrict__ outp)
{
    __shared__ float As[64*17];
    __shared__ float Bs[16*132];

    const int tid  = threadIdx.x;
    const int tx   = tid & 15, ty = tid >> 4;
    const int row0 = blockIdx.y * 64;
    const int col0 = blockIdx.x * 128;
    const int Arow = tid >> 2, Ac = (tid & 3) * 4;
    const int Br   = tid >> 5, Bc = (tid & 31) * 4;

    ull acc[4][4];
    #pragma unroll
    for (int j = 0; j < 4; j++)
        #pragma unroll
        for (int i = 0; i < 4; i++) acc[j][i] = 0ull;

    for (int k0 = 0; k0 < EE; k0 += 16) {
        float4 a4 = *(const float4*)&g_vals[(size_t)(row0 + Arow)*EE + k0 + Ac];
        float4 b0 = *(const float4*)&Wo[(size_t)(k0 + Br    )*EE + col0 + Bc];
        float4 b1 = *(const float4*)&Wo[(size_t)(k0 + Br + 8)*EE + col0 + Bc];
        __syncthreads();
        As[Arow*17 + Ac+0] = a4.x; As[Arow*17 + Ac+1] = a4.y;
        As[Arow*17 + Ac+2] = a4.z; As[Arow*17 + Ac+3] = a4.w;
        *(float4*)&Bs[(Br    )*132 + Bc] = b0;
        *(float4*)&Bs[(Br + 8)*132 + Bc] = b1;
        __syncthreads();
        #pragma unroll
        for (int kk = 0; kk < 16; kk++) {
            ull bp[4];
            #pragma unroll
            for (int i = 0; i < 4; i++)
                bp[i] = *(const ull*)&Bs[kk*132 + 2*tx + 32*i];
            #pragma unroll
            for (int j = 0; j < 4; j++) {
                float a = As[(ty*4+j)*17 + kk];
                ull aa = pk2(a, a);
                #pragma unroll
                for (int i = 0; i < 4; i++)
                    acc[j][i] = fma2(aa, bp[i], acc[j][i]);
            }
        }
    }

    #pragma unroll
    for (int i = 0; i < 4; i++) {
        int c = col0 + 2*tx + 32*i;
        float blo = bo[c], bhi = bo[c+1];
        #pragma unroll
        for (int j = 0; j < 4; j++) {
            int r = row0 + ty*4 + j;
            float lo, hi; upk2(acc[j][i], lo, hi);
            float2 o; o.x = lo + blo; o.y = hi + bhi;
            *(float2*)&outp[(size_t)r*EE + c] = o;
        }
    }
}

// ---------------------------------------------------------------------------
// d_out: [0, B*S*E) = out ; [B*S*E, +B*H*S*S) = attn
// ---------------------------------------------------------------------------
extern "C" void kernel_launch(void* const* d_in, const int* in_sizes, int n_in,
                              void* d_out, int out_size)
{
    const float* x  = (const float*)d_in[0];
    const float* Wq = (const float*)d_in[1];
    const float* bq = (const float*)d_in[2];
    const float* Wk = (const float*)d_in[3];
    const float* bk = (const float*)d_in[4];
    const float* Wv = (const float*)d_in[5];
    const float* bv = (const float*)d_in[6];
    const float* Wo = (const float*)d_in[7];
    const float* bo = (const float*)d_in[8];
    const float* pp = (const float*)d_in[9];
    float* out = (float*)d_out;

    proj_kernel<<<dim3(EE/128, (BB*SS)/64, 3), 256>>>(x, Wq, bq, Wk, bk, Wv, bv);
    knorm_kernel<<<(BHn*SS)/256, 256>>>();

    cudaFuncSetAttribute(attn_kernel,
                         cudaFuncAttributeMaxDynamicSharedMemorySize,
                         SMF * (int)sizeof(float));
    attn_kernel<<<dim3(BHn, SS/QT), 256, SMF * sizeof(float)>>>(
        pp, out + (size_t)BB*SS*EE);

    out_kernel<<<dim3(EE/128, (BB*SS)/64), 256>>>(Wo, bo, out);
}

// round 7
// speedup vs baseline: 2.2110x; 1.4717x over previous
#include <cuda_runtime.h>
#include <cuda_bf16.h>
#include <cstdint>
#include <math.h>

// NOTE: resubmission — R5/R6 failed at the broker level ("GB300 container
// failed twice"), same signature as the Round-0 empty-stub failure; no
// kernel-side evidence was produced. Source is functionally identical to R5.

// Problem constants
#define BB  8
#define SS  1024
#define EE  512
#define HH  8
#define DD  64
#define BHn (BB*HH)          // 64
#define QT  32               // q rows per attention block
#define KT2 256              // k tile cols per attention iteration

typedef unsigned long long ull;

// ---------------------------------------------------------------------------
// f32x2 helpers (attention kernel)
// ---------------------------------------------------------------------------
__device__ __forceinline__ ull pk2(float a, float b) {
    ull r; asm("mov.b64 %0,{%1,%2};" : "=l"(r) : "f"(a), "f"(b)); return r;
}
__device__ __forceinline__ void upk2(ull v, float& a, float& b) {
    asm("mov.b64 {%0,%1},%2;" : "=f"(a), "=f"(b) : "l"(v));
}
__device__ __forceinline__ ull fma2(ull a, ull b, ull c) {
    ull d; asm("fma.rn.f32x2 %0,%1,%2,%3;" : "=l"(d) : "l"(a), "l"(b), "l"(c)); return d;
}

// ---------------------------------------------------------------------------
// mma.sync / ldmatrix helpers (sm_80+, valid on plain sm_100 target)
// ---------------------------------------------------------------------------
__device__ __forceinline__ uint32_t smem_to_u32(const void* smem_ptr) {
    uint32_t addr;
    asm("{ .reg .u64 tmp; cvta.to.shared.u64 tmp, %1; cvt.u32.u64 %0, tmp; }"
        : "=r"(addr) : "l"(smem_ptr));
    return addr;
}

#define LDMAT4(r, addr) \
    asm volatile("ldmatrix.sync.aligned.m8n8.x4.shared.b16 {%0,%1,%2,%3}, [%4];" \
        : "=r"((r)[0]), "=r"((r)[1]), "=r"((r)[2]), "=r"((r)[3]) : "r"(addr))

#define MMA16816(d, a, b) \
    asm volatile("mma.sync.aligned.m16n8k16.row.col.f32.bf16.bf16.f32 " \
        "{%0,%1,%2,%3}, {%4,%5,%6,%7}, {%8,%9}, {%0,%1,%2,%3};" \
        : "+f"((d)[0]), "+f"((d)[1]), "+f"((d)[2]), "+f"((d)[3]) \
        : "r"((a)[0]), "r"((a)[1]), "r"((a)[2]), "r"((a)[3]), \
          "r"((b)[0]), "r"((b)[1]))

// ---------------------------------------------------------------------------
// Scratch
// ---------------------------------------------------------------------------
__device__ float g_q[(size_t)BHn*SS*DD];
__device__ float g_k[(size_t)BHn*SS*DD];
__device__ float g_v[(size_t)BHn*SS*DD];
__device__ float g_kn[BHn*SS];
__device__ float g_vals[(size_t)BB*SS*EE];

__device__ __nv_bfloat16 g_xhi[(size_t)BB*SS*EE];
__device__ __nv_bfloat16 g_xmid[(size_t)BB*SS*EE];
__device__ __nv_bfloat16 g_vhi[(size_t)BB*SS*EE];
__device__ __nv_bfloat16 g_vmid[(size_t)BB*SS*EE];
__device__ __nv_bfloat16 g_wthi[4*EE*EE];    // W^T splits (Wq,Wk,Wv,Wo), [n][k]
__device__ __nv_bfloat16 g_wtmid[4*EE*EE];

// ---------------------------------------------------------------------------
// split: fp32 -> hi/mid bf16. which=0: x -> g_x*, which=1: g_vals -> g_v*
// ---------------------------------------------------------------------------
__global__ void __launch_bounds__(256) split_kernel(
    const float* __restrict__ in, int which)
{
    const float* src = (which == 0) ? in : g_vals;
    __nv_bfloat16* hi  = which ? g_vhi  : g_xhi;
    __nv_bfloat16* mid = which ? g_vmid : g_xmid;

    int i = blockIdx.x * 256 + threadIdx.x;      // float4 index
    float4 v = ((const float4*)src)[i];
    __nv_bfloat16 h0 = __float2bfloat16_rn(v.x);
    __nv_bfloat16 h1 = __float2bfloat16_rn(v.y);
    __nv_bfloat16 h2 = __float2bfloat16_rn(v.z);
    __nv_bfloat16 h3 = __float2bfloat16_rn(v.w);
    __nv_bfloat16 m0 = __float2bfloat16_rn(v.x - __bfloat162float(h0));
    __nv_bfloat16 m1 = __float2bfloat16_rn(v.y - __bfloat162float(h1));
    __nv_bfloat16 m2 = __float2bfloat16_rn(v.z - __bfloat162float(h2));
    __nv_bfloat16 m3 = __float2bfloat16_rn(v.w - __bfloat162float(h3));
    __nv_bfloat16 hb[4] = {h0,h1,h2,h3};
    __nv_bfloat16 mb[4] = {m0,m1,m2,m3};
    *(uint2*)&hi[(size_t)i*4]  = *(const uint2*)hb;
    *(uint2*)&mid[(size_t)i*4] = *(const uint2*)mb;
}

// ---------------------------------------------------------------------------
// split_w: W[512,512] -> W^T hi/mid bf16 [n][k], one matrix per blockIdx.z
// ---------------------------------------------------------------------------
__global__ void __launch_bounds__(256) split_w_kernel(
    const float* __restrict__ W0, const float* __restrict__ W1,
    const float* __restrict__ W2, const float* __restrict__ W3)
{
    const float* W = (blockIdx.z == 0) ? W0 : (blockIdx.z == 1) ? W1
                    : (blockIdx.z == 2) ? W2 : W3;
    __nv_bfloat16* hi  = g_wthi  + (size_t)blockIdx.z * EE * EE;
    __nv_bfloat16* mid = g_wtmid + (size_t)blockIdx.z * EE * EE;

    __shared__ float t[32][33];
    int tx = threadIdx.x & 31, ty = threadIdx.x >> 5;   // 32 x 8
    int k0 = blockIdx.x * 32, n0 = blockIdx.y * 32;
    #pragma unroll
    for (int j = 0; j < 4; j++) {
        int kk = ty + j*8;
        t[kk][tx] = W[(size_t)(k0 + kk)*EE + n0 + tx];
    }
    __syncthreads();
    #pragma unroll
    for (int j = 0; j < 4; j++) {
        int nn = ty + j*8;
        float v = t[tx][nn];
        __nv_bfloat16 h = __float2bfloat16_rn(v);
        __nv_bfloat16 m = __float2bfloat16_rn(v - __bfloat162float(h));
        hi[(size_t)(n0 + nn)*EE + k0 + tx]  = h;
        mid[(size_t)(n0 + nn)*EE + k0 + tx] = m;
    }
}

// ---------------------------------------------------------------------------
// Tensor-core GEMM via mma.sync: C[8192,512] = A @ W + bias
// A = hi+mid bf16 split, 3 MMA chains (hh, hm, mh).
// Block 128x128, 8 warps (4m x 2n), warp tile 32x64, BK=64.
// SMEM rows padded to 144B -> conflict-free ldmatrix.
// mode 0: scatter to g_q/g_k/g_v per blockIdx.z. mode 1: linear to outp (Wo).
// ---------------------------------------------------------------------------
#define TILE_B   18432            // 128 rows * 144 B
#define KP_B     144
#define GM_SMEM  (4*TILE_B)       // 73728 B

__global__ void __launch_bounds__(256) gemm_mma_kernel(
    const float* __restrict__ bias0, const float* __restrict__ bias1,
    const float* __restrict__ bias2,
    float* __restrict__ outp, int mode)
{
    extern __shared__ char smem[];
    char* sAhi  = smem;
    char* sAmid = smem + TILE_B;
    char* sBhi  = smem + 2*TILE_B;
    char* sBmid = smem + 3*TILE_B;
    const uint32_t sb = smem_to_u32(smem);

    const int tid = threadIdx.x;
    const int w = tid >> 5, lane = tid & 31;
    const int wm = w & 3, wn = w >> 2;        // 4m x 2n warp grid
    const int nt = blockIdx.x, mt = blockIdx.y;
    const int z  = (mode == 0) ? blockIdx.z : 3;
    const int row0 = mt * 128, col0 = nt * 128;

    const __nv_bfloat16* Ahi  = (mode == 0) ? g_xhi  : g_vhi;
    const __nv_bfloat16* Amid = (mode == 0) ? g_xmid : g_vmid;
    const __nv_bfloat16* Bhi  = g_wthi  + (size_t)z * EE * EE;
    const __nv_bfloat16* Bmid = g_wtmid + (size_t)z * EE * EE;
    const float* bias = (mode == 1) ? bias0
                       : (z == 0) ? bias0 : (z == 1) ? bias1 : bias2;

    float acc[2][8][4];
    #pragma unroll
    for (int mf = 0; mf < 2; mf++)
        #pragma unroll
        for (int nf = 0; nf < 8; nf++)
            #pragma unroll
            for (int i = 0; i < 4; i++) acc[mf][nf][i] = 0.f;

    // ldmatrix per-lane address components
    // A frag (m16xk16): lanes 0-7 rows0-7, 8-15 rows8-15, 16-31 same + k-half
    const int arow   = wm*32 + (lane & 7) + ((lane >> 3) & 1) * 8;
    const int acolB  = (lane >> 4) * 16;              // +8 k for lanes 16-31
    // B frags ([n][k] layout): mats = n0-7/k0-7, n0-7/k8-15, n8-15/k0-7, n8-15/k8-15
    const int brow   = wn*64 + (lane & 7) + ((lane >> 4) & 1) * 8;
    const int bkB    = ((lane >> 3) & 1) * 16;

    for (int t = 0; t < 8; t++) {
        const int k0 = t * 64;
        __syncthreads();
        #pragma unroll
        for (int j = 0; j < 4; j++) {
            int idx = tid + j*256;
            int rr = idx >> 3, cc = idx & 7;
            size_t aoff = (size_t)(row0 + rr)*EE + k0 + cc*8;
            size_t boff = (size_t)(col0 + rr)*EE + k0 + cc*8;
            int so = rr*KP_B + cc*16;
            *(uint4*)(sAhi  + so) = *(const uint4*)(Ahi  + aoff);
            *(uint4*)(sAmid + so) = *(const uint4*)(Amid + aoff);
            *(uint4*)(sBhi  + so) = *(const uint4*)(Bhi  + boff);
            *(uint4*)(sBmid + so) = *(const uint4*)(Bmid + boff);
        }
        __syncthreads();

        #pragma unroll
        for (int kk = 0; kk < 4; kk++) {
            const int kB = kk*32;
            uint32_t ahi[2][4], amid[2][4];
            #pragma unroll
            for (int mf = 0; mf < 2; mf++) {
                LDMAT4(ahi[mf],  sb + 0*TILE_B + (arow + mf*16)*KP_B + kB + acolB);
                LDMAT4(amid[mf], sb + 1*TILE_B + (arow + mf*16)*KP_B + kB + acolB);
            }
            uint32_t bhi[8][2], bmid[8][2];
            #pragma unroll
            for (int np = 0; np < 4; np++) {
                uint32_t r[4];
                LDMAT4(r, sb + 2*TILE_B + (brow + np*16)*KP_B + kB + bkB);
                bhi[np*2][0] = r[0]; bhi[np*2][1] = r[1];
                bhi[np*2+1][0] = r[2]; bhi[np*2+1][1] = r[3];
                LDMAT4(r, sb + 3*TILE_B + (brow + np*16)*KP_B + kB + bkB);
                bmid[np*2][0] = r[0]; bmid[np*2][1] = r[1];
                bmid[np*2+1][0] = r[2]; bmid[np*2+1][1] = r[3];
            }
            #pragma unroll
            for (int mf = 0; mf < 2; mf++)
                #pragma unroll
                for (int nf = 0; nf < 8; nf++) {
                    MMA16816(acc[mf][nf], ahi[mf],  bhi[nf]);
                    MMA16816(acc[mf][nf], ahi[mf],  bmid[nf]);
                    MMA16816(acc[mf][nf], amid[mf], bhi[nf]);
                }
        }
    }

    // Epilogue: d0,d1 -> (row, c/c+1); d2,d3 -> (row+8, c/c+1)
    const int erow = lane >> 2;
    const int ecol = (lane & 3) * 2;
    #pragma unroll
    for (int mf = 0; mf < 2; mf++) {
        #pragma unroll
        for (int nf = 0; nf < 8; nf++) {
            int r  = row0 + wm*32 + mf*16 + erow;
            int gc = col0 + wn*64 + nf*8 + ecol;
            float bx = bias[gc], by = bias[gc+1];
            float2 o0, o1;
            o0.x = acc[mf][nf][0] + bx; o0.y = acc[mf][nf][1] + by;
            o1.x = acc[mf][nf][2] + bx; o1.y = acc[mf][nf][3] + by;
            if (mode == 0) {
                int head = gc >> 6, dd0 = gc & 63;
                float* scat = (z == 0) ? g_q : (z == 1) ? g_k : g_v;
                int bb0 = r >> 10, ss0 = r & 1023;
                int bb1 = (r+8) >> 10, ss1 = (r+8) & 1023;
                *(float2*)&scat[((size_t)(bb0*HH + head)*SS + ss0)*DD + dd0] = o0;
                *(float2*)&scat[((size_t)(bb1*HH + head)*SS + ss1)*DD + dd0] = o1;
            } else {
                *(float2*)&outp[(size_t)r*EE + gc]     = o0;
                *(float2*)&outp[(size_t)(r+8)*EE + gc] = o1;
            }
        }
    }
}

// ---------------------------------------------------------------------------
// k row norms
// ---------------------------------------------------------------------------
__global__ void __launch_bounds__(256) knorm_kernel()
{
    int r = blockIdx.x * blockDim.x + threadIdx.x;
    if (r >= BHn*SS) return;
    const float* kp = g_k + (size_t)r * DD;
    float s = 0.f;
    #pragma unroll
    for (int i = 0; i < 16; i++) {
        float4 v = *(const float4*)&kp[i*4];
        s += v.x*v.x + v.y*v.y + v.z*v.z + v.w*v.w;
    }
    g_kn[r] = s;
}

// ---------------------------------------------------------------------------
// Fused attention. Softmax phase caches e/rb in registers (2 exp/elem).
// ---------------------------------------------------------------------------
#define SC_F   (QT*SS)
#define KV_F   (KT2*66)
#define QS_F   (QT*65)
#define SMF    (SC_F + KV_F + QS_F + SS)

__global__ void __launch_bounds__(256) attn_kernel(
    const float* __restrict__ pond, float* __restrict__ attn_out)
{
    extern __shared__ float sm[];
    float* sc = sm;
    float* kv = sc + SC_F;
    float* qs = kv + KV_F;
    float* kn = qs + QS_F;

    const int tid = threadIdx.x;
    const int bh  = blockIdx.x;
    const int q0  = blockIdx.y * QT;

    const float p      = pond[0];
    const float sv     = 1.f / (1.f + __expf(-p));
    const float p0     = 1.f - sv, p1 = sv;
    const float invden = 1.f / (p0 + p1 + 1e-7f);

    #pragma unroll
    for (int it = 0; it < 2; it++) {
        int f = tid + it*256;
        int r = f >> 4, c = (f & 15) * 4;
        float4 v = *(const float4*)&g_q[((size_t)bh*SS + q0 + r)*DD + c];
        float* d = qs + r*65 + c;
        d[0]=v.x; d[1]=v.y; d[2]=v.z; d[3]=v.w;
    }
    for (int i = tid; i < SS; i += 256) kn[i] = g_kn[bh*SS + i];

    const int tx = tid & 31;
    const int ty = tid >> 5;

    // ---- scores ----
    const float* kbase = g_k + (size_t)bh*SS*DD;
    for (int kt = 0; kt < 4; kt++) {
        __syncthreads();
        #pragma unroll
        for (int it = 0; it < 16; it++) {
            int f = tid + it*256;
            int r = f >> 4, c = (f & 15) * 4;
            float4 v = *(const float4*)&kbase[(size_t)(kt*KT2 + r)*DD + c];
            float* d = kv + r*65 + c;
            d[0]=v.x; d[1]=v.y; d[2]=v.z; d[3]=v.w;
        }
        __syncthreads();

        ull acc[4][4];
        #pragma unroll
        for (int j = 0; j < 4; j++)
            #pragma unroll
            for (int pp = 0; pp < 4; pp++) acc[j][pp] = 0ull;

        const float* qb = qs + ty*4*65;
        const float* kb = kv + tx*65;
        #pragma unroll 4
        for (int d = 0; d < 64; d++) {
            ull kp0 = pk2(kb[d + 0*65],   kb[d + 32*65]);
            ull kp1 = pk2(kb[d + 64*65],  kb[d + 96*65]);
            ull kp2 = pk2(kb[d + 128*65], kb[d + 160*65]);
            ull kp3 = pk2(kb[d + 192*65], kb[d + 224*65]);
            #pragma unroll
            for (int j = 0; j < 4; j++) {
                float q = qb[j*65 + d];
                ull qq = pk2(q, q);
                acc[j][0] = fma2(qq, kp0, acc[j][0]);
                acc[j][1] = fma2(qq, kp1, acc[j][1]);
                acc[j][2] = fma2(qq, kp2, acc[j][2]);
                acc[j][3] = fma2(qq, kp3, acc[j][3]);
            }
        }
        #pragma unroll
        for (int j = 0; j < 4; j++) {
            float* srow = sc + (ty*4+j)*SS + kt*KT2;
            #pragma unroll
            for (int pp = 0; pp < 4; pp++) {
                float lo, hi; upk2(acc[j][pp], lo, hi);
                srow[tx + 64*pp]      = lo;
                srow[tx + 64*pp + 32] = hi;
            }
        }
    }
    __syncthreads();

    // ---- softmax + RBF + combine: e/rb cached in registers, 2 exp/elem ----
    {
        const int warp = tid >> 5, lane = tid & 31;
        for (int rr = warp; rr < QT; rr += 8) {
            const float* qrow = qs + rr*65;
            float qv = qrow[lane], qv2 = qrow[lane+32];
            float qn = qv*qv + qv2*qv2;
            #pragma unroll
            for (int o = 16; o; o >>= 1) qn += __shfl_xor_sync(~0u, qn, o);

            const float sigma  = fminf(fmaxf(qn, 1e-8f), 1e4f);
            const float invsig = 1.f / sigma;
            float* srow = sc + rr*SS;

            float e[32], rb[32];
            float ssum = 0.f, rsum = 0.f;
            #pragma unroll
            for (int i = 0; i < 32; i++) {
                int c = lane + i*32;
                float s = srow[c];
                float ev = __expf(s * 0.125f);
                float dist = fmaxf(qn + kn[c] - 2.f*s, 0.f);
                float rv = __expf(-dist * invsig);
                e[i] = ev; rb[i] = rv;
                ssum += ev; rsum += rv;
            }
            #pragma unroll
            for (int o = 16; o; o >>= 1) {
                ssum += __shfl_xor_sync(~0u, ssum, o);
                rsum += __shfl_xor_sync(~0u, rsum, o);
            }
            const float cs = p0 * invden / ssum;
            const float cr = p1 * invden / fmaxf(rsum, 1e-8f);

            float* arow = attn_out + ((size_t)bh*SS + q0 + rr)*SS;
            #pragma unroll
            for (int i = 0; i < 32; i++) {
                int c = lane + i*32;
                float a = cs*e[i] + cr*rb[i];
                srow[c] = a;
                arow[c] = a;
            }
        }
    }
    __syncthreads();

    // ---- attn @ V ----
    const int lane = tid & 31, w = tid >> 5;
    const int dg = lane & 7, kg = lane >> 3;

    ull vacc[4][4];
    #pragma unroll
    for (int j = 0; j < 4; j++)
        #pragma unroll
        for (int pp = 0; pp < 4; pp++) vacc[j][pp] = 0ull;

    const float* vbase = g_v + (size_t)bh*SS*DD;
    for (int vt = 0; vt < 4; vt++) {
        __syncthreads();
        #pragma unroll
        for (int it = 0; it < 16; it++) {
            int f = tid + it*256;
            int r = f >> 4, c = (f & 15) * 4;
            float4 v = *(const float4*)&vbase[(size_t)(vt*KT2 + r)*DD + c];
            float* d = kv + r*66 + c;
            d[0]=v.x; d[1]=v.y; d[2]=v.z; d[3]=v.w;
        }
        __syncthreads();

        #pragma unroll 2
        for (int kk = 0; kk < 64; kk++) {
            int kl = kg*64 + ((kk + kg*8) & 63);
            const float* vr = kv + kl*66 + 2*dg;
            ull v0 = *(const ull*)(vr +  0);
            ull v1 = *(const ull*)(vr + 16);
            ull v2 = *(const ull*)(vr + 32);
            ull v3 = *(const ull*)(vr + 48);
            const float* acol = sc + vt*KT2 + kl;
            #pragma unroll
            for (int j = 0; j < 4; j++) {
                float a = acol[(w*4+j)*SS];
                ull aa = pk2(a, a);
                vacc[j][0] = fma2(aa, v0, vacc[j][0]);
                vacc[j][1] = fma2(aa, v1, vacc[j][1]);
                vacc[j][2] = fma2(aa, v2, vacc[j][2]);
                vacc[j][3] = fma2(aa, v3, vacc[j][3]);
            }
        }
    }
    __syncthreads();

    #pragma unroll
    for (int j = 0; j < 4; j++)
        #pragma unroll
        for (int pp = 0; pp < 4; pp++) {
            float lo, hi; upk2(vacc[j][pp], lo, hi);
            float* dst = sc + kg*2048 + (w*4+j)*64 + 2*dg + 16*pp;
            dst[0] = lo; dst[1] = hi;
        }
    __syncthreads();

    const int bb = bh >> 3, hh = bh & 7;
    for (int idx = tid; idx < 2048; idx += 256) {
        float vsum = sc[idx] + sc[2048+idx] + sc[4096+idx] + sc[6144+idx];
        int row = idx >> 6, d = idx & 63;
        g_vals[((size_t)(bb*SS + q0 + row))*EE + hh*DD + d] = vsum;
    }
}

// ---------------------------------------------------------------------------
// d_out: [0, B*S*E) = out ; [B*S*E, +B*H*S*S) = attn
// ---------------------------------------------------------------------------
extern "C" void kernel_launch(void* const* d_in, const int* in_sizes, int n_in,
                              void* d_out, int out_size)
{
    const float* x  = (const float*)d_in[0];
    const float* Wq = (const float*)d_in[1];
    const float* bq = (const float*)d_in[2];
    const float* Wk = (const float*)d_in[3];
    const float* bk = (const float*)d_in[4];
    const float* Wv = (const float*)d_in[5];
    const float* bv = (const float*)d_in[6];
    const float* Wo = (const float*)d_in[7];
    const float* bo = (const float*)d_in[8];
    const float* pp = (const float*)d_in[9];
    float* out = (float*)d_out;

    // 1. splits
    split_kernel<<<(BB*SS*EE/4)/256, 256>>>(x, 0);
    split_w_kernel<<<dim3(EE/32, EE/32, 4), 256>>>(Wq, Wk, Wv, Wo);

    // 2. QKV projections on tensor cores (mma.sync)
    cudaFuncSetAttribute(gemm_mma_kernel,
                         cudaFuncAttributeMaxDynamicSharedMemorySize, GM_SMEM);
    gemm_mma_kernel<<<dim3(EE/128, (BB*SS)/128, 3), 256, GM_SMEM>>>(
        bq, bk, bv, nullptr, 0);

    // 3. attention
    knorm_kernel<<<(BHn*SS)/256, 256>>>();
    cudaFuncSetAttribute(attn_kernel,
                         cudaFuncAttributeMaxDynamicSharedMemorySize,
                         SMF * (int)sizeof(float));
    attn_kernel<<<dim3(BHn, SS/QT), 256, SMF * sizeof(float)>>>(
        pp, out + (size_t)BB*SS*EE);

    // 4. output projection
    split_kernel<<<(BB*SS*EE/4)/256, 256>>>(nullptr, 1);
    gemm_mma_kernel<<<dim3(EE/128, (BB*SS)/128, 1), 256, GM_SMEM>>>(
        bo, nullptr, nullptr, out, 1);
}

// round 10
// speedup vs baseline: 3.0185x; 1.3652x over previous
#include <cuda_runtime.h>
#include <cuda_bf16.h>
#include <cstdint>
#include <math.h>

// NOTE: 3rd submission of the R8 change-set. R8/R9 died at the broker level
// ("GB300 container failed twice") with no kernel-side evidence; precedent
// R5/R6->R7 showed identical source fail/fail/pass. Audited 3x for hang /
// alignment / resource faults: none. AT_SMEM=227968 B < 232448 B opt-in cap.

// Problem constants
#define BB  8
#define SS  1024
#define EE  512
#define HH  8
#define DD  64
#define BHn (BB*HH)          // 64
#define QT  32               // q rows per attention block

// ---------------------------------------------------------------------------
// mma.sync / ldmatrix helpers (sm_80+, valid on plain sm_100 target)
// ---------------------------------------------------------------------------
__device__ __forceinline__ uint32_t smem_to_u32(const void* smem_ptr) {
    uint32_t addr;
    asm("{ .reg .u64 tmp; cvta.to.shared.u64 tmp, %1; cvt.u32.u64 %0, tmp; }"
        : "=r"(addr) : "l"(smem_ptr));
    return addr;
}

#define LDMAT4(r, addr) \
    asm volatile("ldmatrix.sync.aligned.m8n8.x4.shared.b16 {%0,%1,%2,%3}, [%4];" \
        : "=r"((r)[0]), "=r"((r)[1]), "=r"((r)[2]), "=r"((r)[3]) : "r"(addr))

#define LDMAT4T(r, addr) \
    asm volatile("ldmatrix.sync.aligned.m8n8.x4.trans.shared.b16 {%0,%1,%2,%3}, [%4];" \
        : "=r"((r)[0]), "=r"((r)[1]), "=r"((r)[2]), "=r"((r)[3]) : "r"(addr))

#define MMA16816(d, a, b) \
    asm volatile("mma.sync.aligned.m16n8k16.row.col.f32.bf16.bf16.f32 " \
        "{%0,%1,%2,%3}, {%4,%5,%6,%7}, {%8,%9}, {%0,%1,%2,%3};" \
        : "+f"((d)[0]), "+f"((d)[1]), "+f"((d)[2]), "+f"((d)[3]) \
        : "r"((a)[0]), "r"((a)[1]), "r"((a)[2]), "r"((a)[3]), \
          "r"((b)[0]), "r"((b)[1]))

// ---------------------------------------------------------------------------
// Scratch
// ---------------------------------------------------------------------------
__device__ float g_q[(size_t)BHn*SS*DD];
__device__ float g_k[(size_t)BHn*SS*DD];
__device__ float g_v[(size_t)BHn*SS*DD];
__device__ float g_kn[BHn*SS];
__device__ float g_vals[(size_t)BB*SS*EE];

__device__ __nv_bfloat16 g_xhi[(size_t)BB*SS*EE];
__device__ __nv_bfloat16 g_xmid[(size_t)BB*SS*EE];
__device__ __nv_bfloat16 g_vhi[(size_t)BB*SS*EE];
__device__ __nv_bfloat16 g_vmid[(size_t)BB*SS*EE];
__device__ __nv_bfloat16 g_wthi[4*EE*EE];    // W^T splits (Wq,Wk,Wv,Wo), [n][k]
__device__ __nv_bfloat16 g_wtmid[4*EE*EE];

// q/k/v bf16 splits for attention mma, [BH][S][D]
__device__ __nv_bfloat16 g_sq_hi[(size_t)BHn*SS*DD];
__device__ __nv_bfloat16 g_sq_mid[(size_t)BHn*SS*DD];
__device__ __nv_bfloat16 g_sk_hi[(size_t)BHn*SS*DD];
__device__ __nv_bfloat16 g_sk_mid[(size_t)BHn*SS*DD];
__device__ __nv_bfloat16 g_sv_hi[(size_t)BHn*SS*DD];
__device__ __nv_bfloat16 g_sv_mid[(size_t)BHn*SS*DD];

__device__ __forceinline__ void split_store2(
    __nv_bfloat16* hi, __nv_bfloat16* mid, size_t i, float2 o)
{
    __nv_bfloat16 hx = __float2bfloat16_rn(o.x), hy = __float2bfloat16_rn(o.y);
    __nv_bfloat16 mx = __float2bfloat16_rn(o.x - __bfloat162float(hx));
    __nv_bfloat16 my = __float2bfloat16_rn(o.y - __bfloat162float(hy));
    __nv_bfloat162 h; h.x = hx; h.y = hy;
    __nv_bfloat162 m; m.x = mx; m.y = my;
    *(__nv_bfloat162*)&hi[i]  = h;
    *(__nv_bfloat162*)&mid[i] = m;
}

// ---------------------------------------------------------------------------
// split: fp32 -> hi/mid bf16. which=0: x -> g_x*, which=1: g_vals -> g_v*
// ---------------------------------------------------------------------------
__global__ void __launch_bounds__(256) split_kernel(
    const float* __restrict__ in, int which)
{
    const float* src = (which == 0) ? in : g_vals;
    __nv_bfloat16* hi  = which ? g_vhi  : g_xhi;
    __nv_bfloat16* mid = which ? g_vmid : g_xmid;

    int i = blockIdx.x * 256 + threadIdx.x;
    float4 v = ((const float4*)src)[i];
    __nv_bfloat16 h0 = __float2bfloat16_rn(v.x);
    __nv_bfloat16 h1 = __float2bfloat16_rn(v.y);
    __nv_bfloat16 h2 = __float2bfloat16_rn(v.z);
    __nv_bfloat16 h3 = __float2bfloat16_rn(v.w);
    __nv_bfloat16 m0 = __float2bfloat16_rn(v.x - __bfloat162float(h0));
    __nv_bfloat16 m1 = __float2bfloat16_rn(v.y - __bfloat162float(h1));
    __nv_bfloat16 m2 = __float2bfloat16_rn(v.z - __bfloat162float(h2));
    __nv_bfloat16 m3 = __float2bfloat16_rn(v.w - __bfloat162float(h3));
    __nv_bfloat16 hb[4] = {h0,h1,h2,h3};
    __nv_bfloat16 mb[4] = {m0,m1,m2,m3};
    *(uint2*)&hi[(size_t)i*4]  = *(const uint2*)hb;
    *(uint2*)&mid[(size_t)i*4] = *(const uint2*)mb;
}

// ---------------------------------------------------------------------------
// split_w: W[512,512] -> W^T hi/mid bf16 [n][k], one matrix per blockIdx.z
// ---------------------------------------------------------------------------
__global__ void __launch_bounds__(256) split_w_kernel(
    const float* __restrict__ W0, const float* __restrict__ W1,
    const float* __restrict__ W2, const float* __restrict__ W3)
{
    const float* W = (blockIdx.z == 0) ? W0 : (blockIdx.z == 1) ? W1
                    : (blockIdx.z == 2) ? W2 : W3;
    __nv_bfloat16* hi  = g_wthi  + (size_t)blockIdx.z * EE * EE;
    __nv_bfloat16* mid = g_wtmid + (size_t)blockIdx.z * EE * EE;

    __shared__ float t[32][33];
    int tx = threadIdx.x & 31, ty = threadIdx.x >> 5;
    int k0 = blockIdx.x * 32, n0 = blockIdx.y * 32;
    #pragma unroll
    for (int j = 0; j < 4; j++) {
        int kk = ty + j*8;
        t[kk][tx] = W[(size_t)(k0 + kk)*EE + n0 + tx];
    }
    __syncthreads();
    #pragma unroll
    for (int j = 0; j < 4; j++) {
        int nn = ty + j*8;
        float v = t[tx][nn];
        __nv_bfloat16 h = __float2bfloat16_rn(v);
        __nv_bfloat16 m = __float2bfloat16_rn(v - __bfloat162float(h));
        hi[(size_t)(n0 + nn)*EE + k0 + tx]  = h;
        mid[(size_t)(n0 + nn)*EE + k0 + tx] = m;
    }
}

// ---------------------------------------------------------------------------
// Tensor-core GEMM via mma.sync: C[8192,512] = A @ W + bias (3-term split)
// mode 0: scatter fp32 + bf16 splits to g_q/k/v + g_s*_hi/mid per blockIdx.z.
// mode 1: linear fp32 to outp (Wo).
// ---------------------------------------------------------------------------
#define TILE_B   18432            // 128 rows * 144 B
#define KP_B     144
#define GM_SMEM  (4*TILE_B)       // 73728 B

__global__ void __launch_bounds__(256) gemm_mma_kernel(
    const float* __restrict__ bias0, const float* __restrict__ bias1,
    const float* __restrict__ bias2,
    float* __restrict__ outp, int mode)
{
    extern __shared__ char smem[];
    char* sAhi  = smem;
    char* sAmid = smem + TILE_B;
    char* sBhi  = smem + 2*TILE_B;
    char* sBmid = smem + 3*TILE_B;
    const uint32_t sb = smem_to_u32(smem);

    const int tid = threadIdx.x;
    const int w = tid >> 5, lane = tid & 31;
    const int wm = w & 3, wn = w >> 2;
    const int nt = blockIdx.x, mt = blockIdx.y;
    const int z  = (mode == 0) ? blockIdx.z : 3;
    const int row0 = mt * 128, col0 = nt * 128;

    const __nv_bfloat16* Ahi  = (mode == 0) ? g_xhi  : g_vhi;
    const __nv_bfloat16* Amid = (mode == 0) ? g_xmid : g_vmid;
    const __nv_bfloat16* Bhi  = g_wthi  + (size_t)z * EE * EE;
    const __nv_bfloat16* Bmid = g_wtmid + (size_t)z * EE * EE;
    const float* bias = (mode == 1) ? bias0
                       : (z == 0) ? bias0 : (z == 1) ? bias1 : bias2;

    float acc[2][8][4];
    #pragma unroll
    for (int mf = 0; mf < 2; mf++)
        #pragma unroll
        for (int nf = 0; nf < 8; nf++)
            #pragma unroll
            for (int i = 0; i < 4; i++) acc[mf][nf][i] = 0.f;

    const int arow   = wm*32 + (lane & 7) + ((lane >> 3) & 1) * 8;
    const int acolB  = (lane >> 4) * 16;
    const int brow   = wn*64 + (lane & 7) + ((lane >> 4) & 1) * 8;
    const int bkB    = ((lane >> 3) & 1) * 16;

    for (int t = 0; t < 8; t++) {
        const int k0 = t * 64;
        __syncthreads();
        #pragma unroll
        for (int j = 0; j < 4; j++) {
            int idx = tid + j*256;
            int rr = idx >> 3, cc = idx & 7;
            size_t aoff = (size_t)(row0 + rr)*EE + k0 + cc*8;
            size_t boff = (size_t)(col0 + rr)*EE + k0 + cc*8;
            int so = rr*KP_B + cc*16;
            *(uint4*)(sAhi  + so) = *(const uint4*)(Ahi  + aoff);
            *(uint4*)(sAmid + so) = *(const uint4*)(Amid + aoff);
            *(uint4*)(sBhi  + so) = *(const uint4*)(Bhi  + boff);
            *(uint4*)(sBmid + so) = *(const uint4*)(Bmid + boff);
        }
        __syncthreads();

        #pragma unroll
        for (int kk = 0; kk < 4; kk++) {
            const int kB = kk*32;
            uint32_t ahi[2][4], amid[2][4];
            #pragma unroll
            for (int mf = 0; mf < 2; mf++) {
                LDMAT4(ahi[mf],  sb + 0*TILE_B + (arow + mf*16)*KP_B + kB + acolB);
                LDMAT4(amid[mf], sb + 1*TILE_B + (arow + mf*16)*KP_B + kB + acolB);
            }
            uint32_t bhi[8][2], bmid[8][2];
            #pragma unroll
            for (int np = 0; np < 4; np++) {
                uint32_t r[4];
                LDMAT4(r, sb + 2*TILE_B + (brow + np*16)*KP_B + kB + bkB);
                bhi[np*2][0] = r[0]; bhi[np*2][1] = r[1];
                bhi[np*2+1][0] = r[2]; bhi[np*2+1][1] = r[3];
                LDMAT4(r, sb + 3*TILE_B + (brow + np*16)*KP_B + kB + bkB);
                bmid[np*2][0] = r[0]; bmid[np*2][1] = r[1];
                bmid[np*2+1][0] = r[2]; bmid[np*2+1][1] = r[3];
            }
            #pragma unroll
            for (int mf = 0; mf < 2; mf++)
                #pragma unroll
                for (int nf = 0; nf < 8; nf++) {
                    MMA16816(acc[mf][nf], ahi[mf],  bhi[nf]);
                    MMA16816(acc[mf][nf], ahi[mf],  bmid[nf]);
                    MMA16816(acc[mf][nf], amid[mf], bhi[nf]);
                }
        }
    }

    const int erow = lane >> 2;
    const int ecol = (lane & 3) * 2;
    #pragma unroll
    for (int mf = 0; mf < 2; mf++) {
        #pragma unroll
        for (int nf = 0; nf < 8; nf++) {
            int r  = row0 + wm*32 + mf*16 + erow;
            int gc = col0 + wn*64 + nf*8 + ecol;
            float bx = bias[gc], by = bias[gc+1];
            float2 o0, o1;
            o0.x = acc[mf][nf][0] + bx; o0.y = acc[mf][nf][1] + by;
            o1.x = acc[mf][nf][2] + bx; o1.y = acc[mf][nf][3] + by;
            if (mode == 0) {
                int head = gc >> 6, dd0 = gc & 63;
                float* scat = (z == 0) ? g_q : (z == 1) ? g_k : g_v;
                __nv_bfloat16* sph = (z == 0) ? g_sq_hi  : (z == 1) ? g_sk_hi  : g_sv_hi;
                __nv_bfloat16* spm = (z == 0) ? g_sq_mid : (z == 1) ? g_sk_mid : g_sv_mid;
                int bb0 = r >> 10, ss0 = r & 1023;
                int bb1 = (r+8) >> 10, ss1 = (r+8) & 1023;
                size_t i0 = ((size_t)(bb0*HH + head)*SS + ss0)*DD + dd0;
                size_t i1 = ((size_t)(bb1*HH + head)*SS + ss1)*DD + dd0;
                *(float2*)&scat[i0] = o0;
                *(float2*)&scat[i1] = o1;
                split_store2(sph, spm, i0, o0);
                split_store2(sph, spm, i1, o1);
            } else {
                *(float2*)&outp[(size_t)r*EE + gc]     = o0;
                *(float2*)&outp[(size_t)(r+8)*EE + gc] = o1;
            }
        }
    }
}

// ---------------------------------------------------------------------------
// k row norms
// ---------------------------------------------------------------------------
__global__ void __launch_bounds__(256) knorm_kernel()
{
    int r = blockIdx.x * blockDim.x + threadIdx.x;
    if (r >= BHn*SS) return;
    const float* kp = g_k + (size_t)r * DD;
    float s = 0.f;
    #pragma unroll
    for (int i = 0; i < 16; i++) {
        float4 v = *(const float4*)&kp[i*4];
        s += v.x*v.x + v.y*v.y + v.z*v.z + v.w*v.w;
    }
    g_kn[r] = s;
}

// ---------------------------------------------------------------------------
// Fused attention v2: scores + attn@V on tensor cores (3-term bf16 split).
//
// SMEM layout (bytes):
//   [0, 132608)        scf: 32 rows x 1036 fp32 (stride 4144 B) — raw scores.
//                      After softmax, row r holds attn-hi bf16 at +0 (2048 B)
//                      and attn-mid bf16 at +2080 (2048 B), same 4144 stride.
//                      (4144 mod 128 = 48 -> 8-row ldmatrix conflict-free)
//   [132608, 206336)   kv: k/v tile splits, 256 rows x 144 B, hi at +0,
//                      mid at +36864. Reused as 8x2048-float AV partials.
//   [206336, 214656)   qs: 32 x 65 fp32 (q tile, for q-norms)
//   [214656, 223872)   qsp: q splits, 32 rows x 144 B; hi +0, mid +4608
//   [223872, 227968)   kn: 1024 fp32
// ---------------------------------------------------------------------------
#define SCB      4144             // sc row stride bytes
#define SC_SF    1036             // sc row stride floats
#define KV_OFF   132608
#define KVM_OFF  36864            // mid offset within kv
#define QS_OFF   206336
#define QSP_OFF  214656
#define QSPM_OFF 4608
#define KN_OFF   223872
#define AT_SMEM  227968

__global__ void __launch_bounds__(256, 1) attn_kernel(
    const float* __restrict__ pond, float* __restrict__ attn_out)
{
    extern __shared__ char smem[];
    const uint32_t sb = smem_to_u32(smem);
    float* scf = (float*)smem;
    float* qs  = (float*)(smem + QS_OFF);
    float* kn  = (float*)(smem + KN_OFF);

    const int tid = threadIdx.x;
    const int w = tid >> 5, lane = tid & 31;
    const int bh = blockIdx.x;
    const int q0 = blockIdx.y * QT;

    const float p      = pond[0];
    const float sv     = 1.f / (1.f + __expf(-p));
    const float p0     = 1.f - sv, p1 = sv;
    const float invden = 1.f / (p0 + p1 + 1e-7f);

    // ---- load q fp32 (norms), q splits, k norms ----
    #pragma unroll
    for (int it = 0; it < 2; it++) {
        int f = tid + it*256;
        int r = f >> 4, c = (f & 15) * 4;
        float4 v = *(const float4*)&g_q[((size_t)bh*SS + q0 + r)*DD + c];
        float* d = qs + r*65 + c;
        d[0]=v.x; d[1]=v.y; d[2]=v.z; d[3]=v.w;
    }
    {
        int r = tid >> 3, cB = (tid & 7) * 16;
        size_t gb = (((size_t)bh*SS + q0 + r)*DD)*2 + cB;
        *(uint4*)(smem + QSP_OFF + r*KP_B + cB) =
            *(const uint4*)((const char*)g_sq_hi + gb);
        *(uint4*)(smem + QSP_OFF + QSPM_OFF + r*KP_B + cB) =
            *(const uint4*)((const char*)g_sq_mid + gb);
    }
    for (int i = tid; i < SS; i += 256) kn[i] = g_kn[bh*SS + i];

    // ldmatrix lane components
    const int frow = lane & 7;
    const int abit = (lane >> 3) & 1;
    const int hbit = (lane >> 4) & 1;
    const int a_row = frow + abit*8;     // A non-trans & B trans row component
    const int a_cB  = hbit*16;           // A non-trans & B trans col component
    const int b_row = frow + hbit*8;     // B non-trans ([n][k]) row component
    const int b_cB  = abit*16;

    // ---- scores: per kt tile of 256 k-cols, warp w owns 32 cols ----
    for (int kt = 0; kt < 4; kt++) {
        __syncthreads();
        #pragma unroll
        for (int it = 0; it < 8; it++) {
            int idx = tid + it*256;
            int r = idx >> 3, cB = (idx & 7) * 16;
            size_t gb = (((size_t)bh*SS + kt*256 + r)*DD)*2 + cB;
            *(uint4*)(smem + KV_OFF + r*KP_B + cB) =
                *(const uint4*)((const char*)g_sk_hi + gb);
            *(uint4*)(smem + KV_OFF + KVM_OFF + r*KP_B + cB) =
                *(const uint4*)((const char*)g_sk_mid + gb);
        }
        __syncthreads();

        float sacc[2][4][4];
        #pragma unroll
        for (int mf = 0; mf < 2; mf++)
            #pragma unroll
            for (int nf = 0; nf < 4; nf++)
                #pragma unroll
                for (int i = 0; i < 4; i++) sacc[mf][nf][i] = 0.f;

        #pragma unroll
        for (int kc = 0; kc < 4; kc++) {
            const int kB = kc*32;
            uint32_t qh[2][4], qm[2][4];
            #pragma unroll
            for (int mf = 0; mf < 2; mf++) {
                LDMAT4(qh[mf], sb + QSP_OFF + (a_row + mf*16)*KP_B + kB + a_cB);
                LDMAT4(qm[mf], sb + QSP_OFF + QSPM_OFF + (a_row + mf*16)*KP_B + kB + a_cB);
            }
            uint32_t kh[4][2], km[4][2];
            #pragma unroll
            for (int np = 0; np < 2; np++) {
                uint32_t r4[4];
                LDMAT4(r4, sb + KV_OFF + (w*32 + np*16 + b_row)*KP_B + kB + b_cB);
                kh[np*2][0] = r4[0]; kh[np*2][1] = r4[1];
                kh[np*2+1][0] = r4[2]; kh[np*2+1][1] = r4[3];
                LDMAT4(r4, sb + KV_OFF + KVM_OFF + (w*32 + np*16 + b_row)*KP_B + kB + b_cB);
                km[np*2][0] = r4[0]; km[np*2][1] = r4[1];
                km[np*2+1][0] = r4[2]; km[np*2+1][1] = r4[3];
            }
            #pragma unroll
            for (int mf = 0; mf < 2; mf++)
                #pragma unroll
                for (int nf = 0; nf < 4; nf++) {
                    MMA16816(sacc[mf][nf], qh[mf], kh[nf]);
                    MMA16816(sacc[mf][nf], qh[mf], km[nf]);
                    MMA16816(sacc[mf][nf], qm[mf], kh[nf]);
                }
        }
        // epilogue -> scf
        const int er = lane >> 2, ec = (lane & 3) * 2;
        #pragma unroll
        for (int mf = 0; mf < 2; mf++)
            #pragma unroll
            for (int nf = 0; nf < 4; nf++) {
                int row = mf*16 + er;
                int col = kt*256 + w*32 + nf*8 + ec;
                float* d0 = scf + row*SC_SF + col;
                d0[0] = sacc[mf][nf][0]; d0[1] = sacc[mf][nf][1];
                float* d1 = scf + (row+8)*SC_SF + col;
                d1[0] = sacc[mf][nf][2]; d1[1] = sacc[mf][nf][3];
            }
    }
    __syncthreads();

    // ---- softmax + RBF + combine; write attn fp32 + in-place bf16 split ----
    for (int rr = w; rr < QT; rr += 8) {
        const float* qrow = qs + rr*65;
        float qv = qrow[lane], qv2 = qrow[lane+32];
        float qn = qv*qv + qv2*qv2;
        #pragma unroll
        for (int o = 16; o; o >>= 1) qn += __shfl_xor_sync(~0u, qn, o);

        const float sigma  = fminf(fmaxf(qn, 1e-8f), 1e4f);
        const float invsig = 1.f / sigma;
        const float* srow = scf + rr*SC_SF;

        float e[32], rb[32];
        float ssum = 0.f, rsum = 0.f;
        #pragma unroll
        for (int i = 0; i < 32; i++) {
            int c = lane + i*32;
            float s = srow[c];
            float ev = __expf(s * 0.125f);
            float dist = fmaxf(qn + kn[c] - 2.f*s, 0.f);
            float rv = __expf(-dist * invsig);
            e[i] = ev; rb[i] = rv;
            ssum += ev; rsum += rv;
        }
        #pragma unroll
        for (int o = 16; o; o >>= 1) {
            ssum += __shfl_xor_sync(~0u, ssum, o);
            rsum += __shfl_xor_sync(~0u, rsum, o);
        }
        const float cs = p0 * invden / ssum;
        const float cr = p1 * invden / fmaxf(rsum, 1e-8f);

        float* arow = attn_out + ((size_t)bh*SS + q0 + rr)*SS;
        char* hrow = smem + rr*SCB;
        char* mrow = smem + rr*SCB + 2080;
        #pragma unroll
        for (int i = 0; i < 32; i++) {
            int c = lane + i*32;
            float a = cs*e[i] + cr*rb[i];
            arow[c] = a;
            __nv_bfloat16 h = __float2bfloat16_rn(a);
            __nv_bfloat16 m = __float2bfloat16_rn(a - __bfloat162float(h));
            *(__nv_bfloat16*)(hrow + c*2) = h;
            *(__nv_bfloat16*)(mrow + c*2) = m;
        }
    }

    // ---- attn @ V on tensor cores: warp w owns k-slice [w*32,+32) per tile ----
    float vacc[2][8][4];
    #pragma unroll
    for (int mf = 0; mf < 2; mf++)
        #pragma unroll
        for (int nf = 0; nf < 8; nf++)
            #pragma unroll
            for (int i = 0; i < 4; i++) vacc[mf][nf][i] = 0.f;

    for (int vt = 0; vt < 4; vt++) {
        __syncthreads();
        #pragma unroll
        for (int it = 0; it < 8; it++) {
            int idx = tid + it*256;
            int r = idx >> 3, cB = (idx & 7) * 16;
            size_t gb = (((size_t)bh*SS + vt*256 + r)*DD)*2 + cB;
            *(uint4*)(smem + KV_OFF + r*KP_B + cB) =
                *(const uint4*)((const char*)g_sv_hi + gb);
            *(uint4*)(smem + KV_OFF + KVM_OFF + r*KP_B + cB) =
                *(const uint4*)((const char*)g_sv_mid + gb);
        }
        __syncthreads();

        #pragma unroll
        for (int kc2 = 0; kc2 < 2; kc2++) {
            const int kloc = w*32 + kc2*16;          // tile-local k base
            const int kgB  = (vt*256 + kloc)*2;      // attn-row byte offset
            uint32_t ah[2][4], am[2][4];
            #pragma unroll
            for (int mf = 0; mf < 2; mf++) {
                LDMAT4(ah[mf], sb + (a_row + mf*16)*SCB + kgB + a_cB);
                LDMAT4(am[mf], sb + (a_row + mf*16)*SCB + 2080 + kgB + a_cB);
            }
            // V [k][n] via trans ldmatrix: rows = k (a_row comp), col = n bytes
            uint32_t vh[8][2], vm[8][2];
            #pragma unroll
            for (int nb = 0; nb < 4; nb++) {
                uint32_t r4[4];
                LDMAT4T(r4, sb + KV_OFF + (kloc + a_row)*KP_B + nb*32 + a_cB);
                vh[nb*2][0] = r4[0]; vh[nb*2][1] = r4[1];
                vh[nb*2+1][0] = r4[2]; vh[nb*2+1][1] = r4[3];
                LDMAT4T(r4, sb + KV_OFF + KVM_OFF + (kloc + a_row)*KP_B + nb*32 + a_cB);
                vm[nb*2][0] = r4[0]; vm[nb*2][1] = r4[1];
                vm[nb*2+1][0] = r4[2]; vm[nb*2+1][1] = r4[3];
            }
            #pragma unroll
            for (int mf = 0; mf < 2; mf++)
                #pragma unroll
                for (int nf = 0; nf < 8; nf++) {
                    MMA16816(vacc[mf][nf], ah[mf], vh[nf]);
                    MMA16816(vacc[mf][nf], ah[mf], vm[nf]);
                    MMA16816(vacc[mf][nf], am[mf], vh[nf]);
                }
        }
    }
    __syncthreads();

    // store per-warp partials (m32 x n64 each) into kv region, then reduce
    {
        float* part = (float*)(smem + KV_OFF) + w*2048;
        const int er = lane >> 2, ec = (lane & 3) * 2;
        #pragma unroll
        for (int mf = 0; mf < 2; mf++)
            #pragma unroll
            for (int nf = 0; nf < 8; nf++) {
                int row = mf*16 + er, col = nf*8 + ec;
                float2 lo; lo.x = vacc[mf][nf][0]; lo.y = vacc[mf][nf][1];
                float2 hi; hi.x = vacc[mf][nf][2]; hi.y = vacc[mf][nf][3];
                *(float2*)(part + row*64 + col)     = lo;
                *(float2*)(part + (row+8)*64 + col) = hi;
            }
    }
    __syncthreads();
    {
        const int bb = bh >> 3, hh = bh & 7;
        const float* pbase = (const float*)(smem + KV_OFF);
        for (int idx = tid; idx < 2048; idx += 256) {
            float s = 0.f;
            #pragma unroll
            for (int ww = 0; ww < 8; ww++) s += pbase[ww*2048 + idx];
            int row = idx >> 6, d = idx & 63;
            g_vals[((size_t)(bb*SS + q0 + row))*EE + hh*DD + d] = s;
        }
    }
}

// ---------------------------------------------------------------------------
// d_out: [0, B*S*E) = out ; [B*S*E, +B*H*S*S) = attn
// ---------------------------------------------------------------------------
extern "C" void kernel_launch(void* const* d_in, const int* in_sizes, int n_in,
                              void* d_out, int out_size)
{
    const float* x  = (const float*)d_in[0];
    const float* Wq = (const float*)d_in[1];
    const float* bq = (const float*)d_in[2];
    const float* Wk = (const float*)d_in[3];
    const float* bk = (const float*)d_in[4];
    const float* Wv = (const float*)d_in[5];
    const float* bv = (const float*)d_in[6];
    const float* Wo = (const float*)d_in[7];
    const float* bo = (const float*)d_in[8];
    const float* pp = (const float*)d_in[9];
    float* out = (float*)d_out;

    // 1. splits
    split_kernel<<<(BB*SS*EE/4)/256, 256>>>(x, 0);
    split_w_kernel<<<dim3(EE/32, EE/32, 4), 256>>>(Wq, Wk, Wv, Wo);

    // 2. QKV projections (also emit q/k/v bf16 splits)
    cudaFuncSetAttribute(gemm_mma_kernel,
                         cudaFuncAttributeMaxDynamicSharedMemorySize, GM_SMEM);
    gemm_mma_kernel<<<dim3(EE/128, (BB*SS)/128, 3), 256, GM_SMEM>>>(
        bq, bk, bv, nullptr, 0);

    // 3. attention (tensor-core scores + AV)
    knorm_kernel<<<(BHn*SS)/256, 256>>>();
    cudaFuncSetAttribute(attn_kernel,
                         cudaFuncAttributeMaxDynamicSharedMemorySize, AT_SMEM);
    attn_kernel<<<dim3(BHn, SS/QT), 256, AT_SMEM>>>(
        pp, out + (size_t)BB*SS*EE);

    // 4. output projection
    split_kernel<<<(BB*SS*EE/4)/256, 256>>>(nullptr, 1);
    gemm_mma_kernel<<<dim3(EE/128, (BB*SS)/128, 1), 256, GM_SMEM>>>(
        bo, nullptr, nullptr, out, 1);
}